// round 10
// baseline (speedup 1.0000x reference)
#include <cuda_runtime.h>
#include <math.h>

#define LIST_CAP    1024
#define BLOOM_WORDS 256            // 8192 bits
#define BLOOM_MASK  8191u
#define EPT         8              // edges per thread in scan (R6-proven)
#define HASH_SLOTS  2048
#define HASH_MASK   2047
#define SV_CAP      4096           // floats for s_v (nBQ*D <= 4096 expected)

__device__ int4 g_list[LIST_CAP];  // (bq, t, dst, 0)
__device__ int  g_cnt;             // reset by k_fix each call

__device__ __forceinline__ float final_elem(float a1, float a2)
{
    float t1 = 1.0f / (1.0f + __expf(-a1));
    float t2 = 1.0f / (1.0f + __expf(-a2));
    float tp = t1 * t2;
    const float EPS = 1e-10f;
    return __logf((tp + EPS) / (1.0f - tp + EPS));
}

// K1: blocks [0, SB): bloom-filtered edge scan, 8 edges/thread; match path is
// just append (bq,t,dst) — no math, no dense accumulator.
// Blocks [SB, ...): const-fill out with final_elem(0,0).
__global__ void k_main(const int* __restrict__ e_index,
                       const int* __restrict__ r_index,
                       const int* __restrict__ edge_index,
                       const int* __restrict__ edge_type,
                       float* __restrict__ out,
                       int E, int nBQ, int N, int outN, int SB, int FB)
{
    int tid = threadIdx.x;
    int bid = blockIdx.x;

    if (bid < SB) {
        __shared__ int      s_e[64];
        __shared__ unsigned s_bloom[BLOOM_WORDS];
        for (int i = tid; i < BLOOM_WORDS; i += blockDim.x) s_bloom[i] = 0u;
        __syncthreads();
        if (tid < nBQ) {
            int ev = e_index[tid];
            s_e[tid] = ev;
            unsigned h = (unsigned)ev & BLOOM_MASK;
            atomicOr(&s_bloom[h >> 5], 1u << (h & 31u));
        }
        __syncthreads();

        int base = (bid * blockDim.x + tid) * EPT;
        int srcs[EPT];
        if (base + EPT - 1 < E) {
            #pragma unroll
            for (int v = 0; v < EPT / 4; v++) {
                int4 a = *(const int4*)(edge_index + base + v * 4);
                srcs[v*4+0]=a.x; srcs[v*4+1]=a.y; srcs[v*4+2]=a.z; srcs[v*4+3]=a.w;
            }
        } else {
            #pragma unroll
            for (int j = 0; j < EPT; j++)
                srcs[j] = (base + j < E) ? edge_index[base + j] : -1;
        }

        #pragma unroll
        for (int j = 0; j < EPT; j++) {
            int src = srcs[j];
            if (src < 0) continue;
            unsigned h = (unsigned)src & BLOOM_MASK;
            if (!((s_bloom[h >> 5] >> (h & 31u)) & 1u)) continue;
            // exact check (bloom FPs drop out); runs only on ~0.4% of edges
            unsigned long long mm = 0ull;
            for (int bq = 0; bq < nBQ; bq++)
                mm |= ((unsigned long long)(src == s_e[bq])) << bq;
            if (!mm) continue;
            int e   = base + j;
            int t   = edge_type[e];
            int dst = edge_index[E + e];
            while (mm) {
                int bq = __ffsll(mm) - 1;
                mm &= mm - 1;
                int idx = atomicAdd(&g_cnt, 1);
                if (idx < LIST_CAP) g_list[idx] = make_int4(bq, t, dst, 0);
            }
        }
    } else {
        // const fill: final_elem(0,0) = log(0.25/0.75)
        const float cv = -1.0986123f;
        float4 cv4 = make_float4(cv, cv, cv, cv);
        int f  = bid - SB;
        int n4 = outN >> 2;
        float4* out4 = (float4*)out;
        for (int k = f * blockDim.x + tid; k < n4; k += FB * blockDim.x)
            out4[k] = cv4;
        int tail = outN & 3;
        int i = f * blockDim.x + tid;
        if (i < tail) out[(n4 << 2) + i] = cv;
    }
}

// K2 (PDL secondary). PRE-SYNC (overlapped with k_main): build s_v from
// inputs, warm rel_proj into L2, init shared hash. POST-SYNC: speculative
// one-entry-per-thread list load, dot from smem/L2, exact duplicate
// aggregation via smem hash, probe both conjunct keys, store.
__global__ void k_fix(const int* __restrict__ r_index,
                      const float* __restrict__ rel_emb,
                      const float* __restrict__ rel_proj,
                      const float* __restrict__ w_out,
                      float* __restrict__ out,
                      int nBQ, int R, int D, int N)
{
    __shared__ float s_v[SV_CAP];
    __shared__ int   s_hkey[HASH_SLOTS];
    __shared__ float s_hval[HASH_SLOTS];

    int tid = threadIdx.x;

    // ---- pre-sync work (inputs only; overlaps k_main) ----
    for (int i = tid; i < HASH_SLOTS; i += blockDim.x) {
        s_hkey[i] = -1;
        s_hval[i] = 0.0f;
    }
    bool svFits = (nBQ * D <= SV_CAP);
    if (svFits) {
        for (int i = tid; i < nBQ * D; i += blockDim.x) {
            int bq = i / D, d = i - bq * D;
            s_v[i] = rel_emb[(size_t)r_index[bq] * D + d] * w_out[d];
        }
    }
    // warm rel_proj into L2 (loads kept, values discarded)
    {
        int total = R * D;
        for (int i = tid; i < total; i += blockDim.x) {
            float x = __ldg(&rel_proj[i]);
            asm volatile("" :: "f"(x));
        }
    }
    __syncthreads();

    cudaGridDependencySynchronize();

    // ---- post-sync ----
    int  cnt = g_cnt;            // independent back-to-back loads (L2: just written)
    int4 en  = g_list[tid];      // speculative, always in-bounds
    if (cnt > LIST_CAP) cnt = LIST_CAP;
    bool act = (tid < cnt);

    int key = 0;
    float w = 0.0f;
    if (act) {
        const float* pt = rel_proj + (size_t)en.y * D;   // L2-warm
        float s = 0.0f;
        if (svFits) {
            const float* pv = s_v + en.x * D;
            #pragma unroll 16
            for (int d = 0; d < D; d++) s += pv[d] * pt[d];
        } else {
            const float* pr = rel_emb + (size_t)r_index[en.x] * D;
            #pragma unroll 16
            for (int d = 0; d < D; d++) s += pr[d] * w_out[d] * pt[d];
        }
        w   = s;
        key = en.x * N + en.z;
        // hash insert (exact duplicate aggregation)
        int slot = (int)(((unsigned)key * 0x9E3779B1u) & HASH_MASK);
        for (;;) {
            int prev = atomicCAS(&s_hkey[slot], -1, key);
            if (prev == -1 || prev == key) { atomicAdd(&s_hval[slot], w); break; }
            slot = (slot + 1) & HASH_MASK;
        }
    }
    __syncthreads();

    if (act) {
        int b   = en.x >> 1;
        int dst = en.z;
        int k1  = (2 * b) * N + dst;
        int k2  = k1 + N;
        float a1 = 0.0f, a2 = 0.0f;
        int slot = (int)(((unsigned)k1 * 0x9E3779B1u) & HASH_MASK);
        for (;;) {
            int k = s_hkey[slot];
            if (k == k1) { a1 = s_hval[slot]; break; }
            if (k == -1) break;
            slot = (slot + 1) & HASH_MASK;
        }
        slot = (int)(((unsigned)k2 * 0x9E3779B1u) & HASH_MASK);
        for (;;) {
            int k = s_hkey[slot];
            if (k == k2) { a2 = s_hval[slot]; break; }
            if (k == -1) break;
            slot = (slot + 1) & HASH_MASK;
        }
        out[(size_t)b * N + dst] = final_elem(a1, a2);
    }
    __syncthreads();
    if (tid == 0) g_cnt = 0;
}

extern "C" void kernel_launch(void* const* d_in, const int* in_sizes, int n_in,
                              void* d_out, int out_size)
{
    // Input order: e_index, r_index, edge_index, edge_type, [num_nodes], rel_emb, rel_proj, w_out
    const int* e_index    = (const int*)d_in[0];
    const int* r_index    = (const int*)d_in[1];
    const int* edge_index = (const int*)d_in[2];
    const int* edge_type  = (const int*)d_in[3];
    int off = (n_in >= 8) ? 5 : 4;
    const float* rel_emb  = (const float*)d_in[off];
    const float* rel_proj = (const float*)d_in[off + 1];
    const float* w_out    = (const float*)d_in[off + 2];

    int nBQ = in_sizes[0];               // B*2
    int B   = nBQ / 2;
    int E   = in_sizes[3];               // edge_type is [E]
    int D   = in_sizes[off + 2];         // w_out is [D]
    int R   = in_sizes[off] / D;         // rel_emb is [R, D]
    int N   = out_size / B;              // output is [B, N]
    int outN = out_size;

    const int TPB = 256;
    int SB = (E + TPB * EPT - 1) / (TPB * EPT);   // 147 for E=300000
    int n4 = outN >> 2;
    int FB = (n4 + TPB * 2 - 1) / (TPB * 2);      // ~2 float4 iters/thread
    if (FB < 1) FB = 1;
    int grid = SB + FB;

    k_main<<<grid, TPB>>>(e_index, r_index, edge_index, edge_type,
                          (float*)d_out, E, nBQ, N, outN, SB, FB);

    // k_fix via PDL: pre-sync table staging overlaps k_main.
    cudaLaunchConfig_t cfg = {};
    cfg.gridDim  = dim3(1, 1, 1);
    cfg.blockDim = dim3(1024, 1, 1);
    cfg.dynamicSmemBytes = 0;
    cfg.stream = 0;
    cudaLaunchAttribute attr[1];
    attr[0].id = cudaLaunchAttributeProgrammaticStreamSerialization;
    attr[0].val.programmaticStreamSerializationAllowed = 1;
    cfg.attrs = attr;
    cfg.numAttrs = 1;
    cudaLaunchKernelEx(&cfg, k_fix, r_index, rel_emb, rel_proj, w_out,
                       (float*)d_out, nBQ, R, D, N);
}